// round 5
// baseline (speedup 1.0000x reference)
#include <cuda_runtime.h>
#include <cuda_bf16.h>
#include <cstdint>

// B=2, T=2048, C=1024, H=16, D=64, causal MHA, fp32 in/out.
#define BB 2
#define TT 2048
#define CC 1024
#define HH 16
#define DD 64
#define MM (BB*TT)

typedef __nv_bfloat16 bf16;

// ---------------- scratch (allocation-free) ----------------
__device__ bf16 g_xh[MM*CC], g_xl[MM*CC];
__device__ bf16 g_ah[MM*CC], g_al[MM*CC];
__device__ bf16 g_wh[4*CC*CC], g_wl[4*CC*CC];
__device__ bf16 g_qh[BB*HH*TT*DD], g_ql[BB*HH*TT*DD];
__device__ bf16 g_kh[BB*HH*TT*DD], g_kl[BB*HH*TT*DD];
__device__ bf16 g_vh[BB*HH*TT*DD], g_vl[BB*HH*TT*DD];

// ---------------- helpers (sm_80-baseline PTX only) ----------------
__device__ __forceinline__ uint32_t smem_u32(const void* p) {
    return (uint32_t)__cvta_generic_to_shared(p);
}

#define CP16(dst, src) \
    asm volatile("cp.async.cg.shared.global [%0], [%1], 16;" :: "r"(dst), "l"(src) : "memory")
#define CP_COMMIT() asm volatile("cp.async.commit_group;" ::: "memory")
#define CP_WAIT(n)  asm volatile("cp.async.wait_group %0;" :: "n"(n) : "memory")

__device__ __forceinline__ void ldm4(uint32_t* r, uint32_t a) {
    asm volatile("ldmatrix.sync.aligned.m8n8.x4.shared.b16 {%0,%1,%2,%3}, [%4];"
                 : "=r"(r[0]), "=r"(r[1]), "=r"(r[2]), "=r"(r[3]) : "r"(a));
}
__device__ __forceinline__ void ldm4t(uint32_t* r, uint32_t a) {
    asm volatile("ldmatrix.sync.aligned.m8n8.x4.trans.shared.b16 {%0,%1,%2,%3}, [%4];"
                 : "=r"(r[0]), "=r"(r[1]), "=r"(r[2]), "=r"(r[3]) : "r"(a));
}
__device__ __forceinline__ void mma_bf16(float* d, const uint32_t* a, const uint32_t* b) {
    asm volatile("mma.sync.aligned.m16n8k16.row.col.f32.bf16.bf16.f32 "
                 "{%0,%1,%2,%3}, {%4,%5,%6,%7}, {%8,%9}, {%0,%1,%2,%3};"
                 : "+f"(d[0]), "+f"(d[1]), "+f"(d[2]), "+f"(d[3])
                 : "r"(a[0]), "r"(a[1]), "r"(a[2]), "r"(a[3]), "r"(b[0]), "r"(b[1]));
}

__device__ __forceinline__ uint32_t pk2(float a, float b) {
    __nv_bfloat162 t;
    t.x = __float2bfloat16(a); t.y = __float2bfloat16(b);
    return *reinterpret_cast<uint32_t*>(&t);
}
__device__ __forceinline__ void split_st(bf16* hi, bf16* lo, size_t off, float a, float b) {
    bf16 h0 = __float2bfloat16(a), h1 = __float2bfloat16(b);
    *(__nv_bfloat162*)(hi + off) = __nv_bfloat162(h0, h1);
    *(__nv_bfloat162*)(lo + off) =
        __nv_bfloat162(__float2bfloat16(a - __bfloat162float(h0)),
                       __float2bfloat16(b - __bfloat162float(h1)));
}

// ---------------------------------------------------------------------------
__global__ void split_kernel(const float* __restrict__ x,
                             bf16* __restrict__ hi, bf16* __restrict__ lo) {
    int i = blockIdx.x * blockDim.x + threadIdx.x;
    float4 v = ((const float4*)x)[i];
    bf16 h0 = __float2bfloat16(v.x), h1 = __float2bfloat16(v.y);
    bf16 h2 = __float2bfloat16(v.z), h3 = __float2bfloat16(v.w);
    bf16 l0 = __float2bfloat16(v.x - __bfloat162float(h0));
    bf16 l1 = __float2bfloat16(v.y - __bfloat162float(h1));
    bf16 l2 = __float2bfloat16(v.z - __bfloat162float(h2));
    bf16 l3 = __float2bfloat16(v.w - __bfloat162float(h3));
    __nv_bfloat162* hp = (__nv_bfloat162*)(hi + 4*(size_t)i);
    __nv_bfloat162* lp = (__nv_bfloat162*)(lo + 4*(size_t)i);
    hp[0] = __nv_bfloat162(h0, h1); hp[1] = __nv_bfloat162(h2, h3);
    lp[0] = __nv_bfloat162(l0, l1); lp[1] = __nv_bfloat162(l2, l3);
}

// ---------------------------------------------------------------------------
// transpose + split all 4 weights in one launch (grid.z selects matrix)
// ---------------------------------------------------------------------------
__global__ void tsplit_kernel(const float* __restrict__ W0, const float* __restrict__ W1,
                              const float* __restrict__ W2, const float* __restrict__ W3,
                              bf16* __restrict__ hi, bf16* __restrict__ lo) {
    __shared__ float t[32][33];
    int tx = threadIdx.x, ty = threadIdx.y;          // (32, 8)
    int n0 = blockIdx.x * 32, k0 = blockIdx.y * 32;
    int z = blockIdx.z;
    const float* W = (z == 0) ? W0 : (z == 1) ? W1 : (z == 2) ? W2 : W3;
    bf16* hz = hi + (size_t)z * CC * CC;
    bf16* lz = lo + (size_t)z * CC * CC;
#pragma unroll
    for (int i = 0; i < 4; i++)
        t[ty + 8*i][tx] = W[(size_t)(k0 + ty + 8*i) * CC + n0 + tx];
    __syncthreads();
#pragma unroll
    for (int i = 0; i < 4; i++) {
        float v = t[tx][ty + 8*i];
        bf16 h = __float2bfloat16(v);
        bf16 l = __float2bfloat16(v - __bfloat162float(h));
        size_t o = (size_t)(n0 + ty + 8*i) * CC + k0 + tx;
        hz[o] = h; lz[o] = l;
    }
}

// ---------------------------------------------------------------------------
// mma.sync bf16x3 GEMM, occupancy-2 version.
// 128x128 tile, K-chunk 32, 3-stage cp.async, 8 warps (64x32 each), 96KB smem.
// Smem matrix tile: 128 rows x 32 k packed into 64 smem-rows of 128B:
//   phys(r, c) = (r&63)*128 + (((c + 4*(r>>6)) ^ (r&7)) << 4),  c = 16B-chunk 0..3
// (8 consecutive rows hit 8 distinct 16B slots -> conflict-free ldmatrix)
// Stage: Ah(8K) Al(8K) Bh(8K) Bl(8K) = 32KB; 3 stages.
// MODE 0: split-bf16 output remapped to [B,H,T,D], scaled. MODE 1: fp32 [M,N].
// ---------------------------------------------------------------------------
#define GSTG 32768
#define NKT  32

template<int MODE>
__global__ __launch_bounds__(256, 2) void gemm_bf16x3(
    const bf16* __restrict__ Ah, const bf16* __restrict__ Al,
    const bf16* __restrict__ Bh, const bf16* __restrict__ Bl,
    const float* __restrict__ bias,
    float* __restrict__ outF, bf16* __restrict__ outH, bf16* __restrict__ outL,
    float scale)
{
    extern __shared__ char smraw[];
    const uint32_t sbase = smem_u32(smraw);

    int tid = threadIdx.x, lane = tid & 31, wid = tid >> 5;
    int wm = wid & 1, wn = wid >> 1;
    int m0 = blockIdx.y << 7, n0 = blockIdx.x << 7;

    float acc[4][4][4] = {};

    // loader: per matrix 512 16B-chunks / 256 threads = 2 each
    int lr0 = tid >> 2, lc = tid & 3;                 // rows 0..63 / 64..127
    auto load_stage = [&](int kt, int s) {
        uint32_t sb = sbase + (uint32_t)s * GSTG;
#pragma unroll
        for (int i = 0; i < 2; i++) {
            int r = lr0 + i*64;
            uint32_t phys = (uint32_t)((r & 63)*128 + (((lc + ((r >> 6) << 2)) ^ (r & 7)) << 4));
            size_t ga = (size_t)(m0 + r)*CC + kt*32 + lc*8;
            size_t gb = (size_t)(n0 + r)*CC + kt*32 + lc*8;
            CP16(sb +         phys, Ah + ga);
            CP16(sb +  8192 + phys, Al + ga);
            CP16(sb + 16384 + phys, Bh + gb);
            CP16(sb + 24576 + phys, Bl + gb);
        }
        CP_COMMIT();
    };

    load_stage(0, 0);
    load_stage(1, 1);

    int ahalf = lane >> 4;
    int bhalf = (lane >> 3) & 1;
    int arow_b = wm*64 + (lane & 15);
    int brow_b = wn*32 + ((lane >> 4) << 3) + (lane & 7);

    for (int kt = 0; kt < NKT; kt++) {
        CP_WAIT(1);
        __syncthreads();
        if (kt + 2 < NKT) load_stage(kt + 2, (kt + 2) % 3);
        else              CP_COMMIT();                 // keep group numbering

        uint32_t sb = sbase + (uint32_t)(kt % 3) * GSTG;
#pragma unroll
        for (int kk = 0; kk < 2; kk++) {
            uint32_t ahr[4][4], alr[4][4], bhr[2][4], blr[2][4];
#pragma unroll
            for (int mf = 0; mf < 4; mf++) {
                int r = arow_b + mf*16;
                int c = 2*kk + ahalf;
                uint32_t off = (uint32_t)((r & 63)*128 + (((c + ((r >> 6) << 2)) ^ (r & 7)) << 4));
                ldm4(ahr[mf], sb + off);
                ldm4(alr[mf], sb + 8192 + off);
            }
#pragma unroll
            for (int nh = 0; nh < 2; nh++) {
                int r = brow_b + nh*16;
                int c = 2*kk + bhalf;
                uint32_t off = (uint32_t)((r & 63)*128 + (((c + ((r >> 6) << 2)) ^ (r & 7)) << 4));
                ldm4(bhr[nh], sb + 16384 + off);
                ldm4(blr[nh], sb + 24576 + off);
            }
#pragma unroll
            for (int mf = 0; mf < 4; mf++)
#pragma unroll
                for (int nf = 0; nf < 4; nf++) {
                    const uint32_t* ph = bhr[nf >> 1] + (nf & 1)*2;
                    const uint32_t* pl = blr[nf >> 1] + (nf & 1)*2;
                    mma_bf16(acc[mf][nf], ahr[mf], ph);
                    mma_bf16(acc[mf][nf], ahr[mf], pl);
                    mma_bf16(acc[mf][nf], alr[mf], ph);
                }
        }
    }

    int g = lane >> 2, t2 = (lane & 3) * 2;
#pragma unroll
    for (int nf = 0; nf < 4; nf++) {
        int col = n0 + wn*32 + nf*8 + t2;
        float2 bb = *(const float2*)(bias + col);
#pragma unroll
        for (int mf = 0; mf < 4; mf++) {
            int m1 = m0 + wm*64 + mf*16 + g;
            float v0 = acc[mf][nf][0] + bb.x, v1 = acc[mf][nf][1] + bb.y;
            float v2 = acc[mf][nf][2] + bb.x, v3 = acc[mf][nf][3] + bb.y;
            if (MODE == 0) {
                int h = col >> 6, d = col & 63;
                int b1 = m1 >> 11, t1 = m1 & (TT - 1);
                size_t base = ((size_t)(b1*HH + h)*TT) * DD + d;
                split_st(outH, outL, base + (size_t)t1*DD,       v0*scale, v1*scale);
                split_st(outH, outL, base + (size_t)(t1 + 8)*DD, v2*scale, v3*scale);
            } else {
                *(float2*)(outF + (size_t)m1*CC + col)       = make_float2(v0, v1);
                *(float2*)(outF + (size_t)(m1 + 8)*CC + col) = make_float2(v2, v3);
            }
        }
    }
}

// ---------------------------------------------------------------------------
// Tensor-core causal flash attention (bf16x3, fp32 accum). Unchanged (R4).
// ---------------------------------------------------------------------------
__global__ __launch_bounds__(256) void attn_mma()
{
    extern __shared__ char smraw[];
    const uint32_t sb = smem_u32(smraw);
    const uint32_t QH = 0, QL = 16384, ST = 32768, STSZ = 32768;

    int tid = threadIdx.x, lane = tid & 31, w = tid >> 5;
    int bh = blockIdx.y;
    int qt = (int)gridDim.x - 1 - (int)blockIdx.x;
    int q0 = qt * 128;
    int nkt = 2*qt + 2;

    const bf16* Qh = g_qh + (size_t)bh*TT*DD;
    const bf16* Ql = g_ql + (size_t)bh*TT*DD;
    const bf16* Kh = g_kh + (size_t)bh*TT*DD;
    const bf16* Kl = g_kl + (size_t)bh*TT*DD;
    const bf16* Vh = g_vh + (size_t)bh*TT*DD;
    const bf16* Vl = g_vl + (size_t)bh*TT*DD;

    auto load_kv = [&](int kt, int s) {
        uint32_t base = sb + ST + (uint32_t)s * STSZ;
        int k0 = kt * 64;
#pragma unroll
        for (int i = 0; i < 2; i++) {
            int id = tid + i*256;
            int r = id >> 3, c = id & 7;
            uint32_t phys = (uint32_t)(r*128 + ((c ^ (r & 7)) << 4));
            size_t gsrc = (size_t)(k0 + r)*DD + c*8;
            CP16(base +         phys, Kh + gsrc);
            CP16(base +  8192 + phys, Kl + gsrc);
            CP16(base + 16384 + phys, Vh + gsrc);
            CP16(base + 24576 + phys, Vl + gsrc);
        }
        CP_COMMIT();
    };

#pragma unroll
    for (int m = 0; m < 2; m++)
#pragma unroll
        for (int i = 0; i < 4; i++) {
            int id = tid + i*256;
            int r = id >> 3, c = id & 7;
            uint32_t dst = sb + (m ? QL : QH) + (uint32_t)(r*128 + ((c ^ (r & 7)) << 4));
            const bf16* src = (m ? Ql : Qh) + (size_t)(q0 + r)*DD + c*8;
            CP16(dst, src);
        }
    CP_COMMIT();
    load_kv(0, 0);

    CP_WAIT(1);
    __syncthreads();

    uint32_t qfh[4][4], qfl[4][4];
    int arow = w*16 + (lane & 15), ahalf = lane >> 4;
#pragma unroll
    for (int kk = 0; kk < 4; kk++) {
        uint32_t off = (uint32_t)(arow*128 + (((2*kk + ahalf) ^ (arow & 7)) << 4));
        ldm4(qfh[kk], sb + QH + off);
        ldm4(qfl[kk], sb + QL + off);
    }

    float oacc[8][4] = {};
    float mrow0 = -1e30f, mrow1 = -1e30f;
    float lsum0 = 0.f, lsum1 = 0.f;

    int g = lane >> 2, t2 = (lane & 3) * 2;
    int r0g = q0 + 16*w + g, r1g = r0g + 8;
    int bhalf = (lane >> 3) & 1;
    int vi = lane >> 3, vr = lane & 7;

    for (int kt = 0; kt < nkt; kt++) {
        if (kt + 1 < nkt) { load_kv(kt + 1, (kt + 1) & 1); CP_WAIT(1); }
        else              { CP_WAIT(0); }
        __syncthreads();

        int k0 = kt * 64;
        if (k0 <= q0 + 16*w + 15) {
            uint32_t st = sb + ST + (uint32_t)(kt & 1) * STSZ;

            float sacc[8][4] = {};
#pragma unroll
            for (int kk = 0; kk < 4; kk++) {
#pragma unroll
                for (int ng = 0; ng < 4; ng++) {
                    int brow = ng*16 + ((lane >> 4) << 3) + (lane & 7);
                    uint32_t off = (uint32_t)(brow*128 + (((2*kk + bhalf) ^ (brow & 7)) << 4));
                    uint32_t kh4[4], kl4[4];
                    ldm4(kh4, st + off);
                    ldm4(kl4, st + 8192 + off);
                    mma_bf16(sacc[2*ng],   qfh[kk], kh4);
                    mma_bf16(sacc[2*ng],   qfh[kk], kl4);
                    mma_bf16(sacc[2*ng],   qfl[kk], kh4);
                    mma_bf16(sacc[2*ng+1], qfh[kk], kh4 + 2);
                    mma_bf16(sacc[2*ng+1], qfh[kk], kl4 + 2);
                    mma_bf16(sacc[2*ng+1], qfl[kk], kh4 + 2);
                }
            }

            if (k0 + 63 > r0g) {
#pragma unroll
                for (int j = 0; j < 8; j++) {
                    int col = k0 + 8*j + t2;
                    if (col     > r0g) sacc[j][0] = -1e30f;
                    if (col + 1 > r0g) sacc[j][1] = -1e30f;
                    if (col     > r1g) sacc[j][2] = -1e30f;
                    if (col + 1 > r1g) sacc[j][3] = -1e30f;
                }
            }

            float tm0 = -1e30f, tm1 = -1e30f;
#pragma unroll
            for (int j = 0; j < 8; j++) {
                tm0 = fmaxf(tm0, fmaxf(sacc[j][0], sacc[j][1]));
                tm1 = fmaxf(tm1, fmaxf(sacc[j][2], sacc[j][3]));
            }
            tm0 = fmaxf(tm0, __shfl_xor_sync(0xffffffffu, tm0, 1));
            tm0 = fmaxf(tm0, __shfl_xor_sync(0xffffffffu, tm0, 2));
            tm1 = fmaxf(tm1, __shfl_xor_sync(0xffffffffu, tm1, 1));
            tm1 = fmaxf(tm1, __shfl_xor_sync(0xffffffffu, tm1, 2));
            float mn0 = fmaxf(mrow0, tm0), mn1 = fmaxf(mrow1, tm1);
            float c0 = __expf(mrow0 - mn0), c1 = __expf(mrow1 - mn1);
            mrow0 = mn0; mrow1 = mn1;

            float ps0 = 0.f, ps1 = 0.f;
            uint32_t pfh[4][4], pfl[4][4];
#pragma unroll
            for (int kc = 0; kc < 4; kc++) {
#pragma unroll
                for (int jj = 0; jj < 2; jj++) {
                    int j = 2*kc + jj;
                    float p0 = __expf(sacc[j][0] - mn0);
                    float p1 = __expf(sacc[j][1] - mn0);
                    float p2 = __expf(sacc[j][2] - mn1);
                    float p3 = __expf(sacc[j][3] - mn1);
                    ps0 += p0 + p1; ps1 += p2 + p3;
                    float h0 = __bfloat162float(__float2bfloat16(p0));
                    float h1 = __bfloat162float(__float2bfloat16(p1));
                    float h2 = __bfloat162float(__float2bfloat16(p2));
                    float h3 = __bfloat162float(__float2bfloat16(p3));
                    pfh[kc][2*jj]   = pk2(h0, h1);
                    pfh[kc][2*jj+1] = pk2(h2, h3);
                    pfl[kc][2*jj]   = pk2(p0 - h0, p1 - h1);
                    pfl[kc][2*jj+1] = pk2(p2 - h2, p3 - h3);
                }
            }
            lsum0 = lsum0 * c0 + ps0;
            lsum1 = lsum1 * c1 + ps1;
#pragma unroll
            for (int j = 0; j < 8; j++) {
                oacc[j][0] *= c0; oacc[j][1] *= c0;
                oacc[j][2] *= c1; oacc[j][3] *= c1;
            }

#pragma unroll
            for (int kc = 0; kc < 4; kc++) {
#pragma unroll
                for (int dg = 0; dg < 4; dg++) {
                    int key = kc*16 + 8*(vi & 1) + vr;
                    int dc = 2*dg + (vi >> 1);
                    uint32_t off = (uint32_t)(key*128 + ((dc ^ (key & 7)) << 4));
                    uint32_t vh4[4], vl4[4];
                    ldm4t(vh4, st + 16384 + off);
                    ldm4t(vl4, st + 24576 + off);
                    mma_bf16(oacc[2*dg],   pfh[kc], vh4);
                    mma_bf16(oacc[2*dg],   pfh[kc], vl4);
                    mma_bf16(oacc[2*dg],   pfl[kc], vh4);
                    mma_bf16(oacc[2*dg+1], pfh[kc], vh4 + 2);
                    mma_bf16(oacc[2*dg+1], pfh[kc], vl4 + 2);
                    mma_bf16(oacc[2*dg+1], pfl[kc], vh4 + 2);
                }
            }
        }
        __syncthreads();
    }

    lsum0 += __shfl_xor_sync(0xffffffffu, lsum0, 1);
    lsum0 += __shfl_xor_sync(0xffffffffu, lsum0, 2);
    lsum1 += __shfl_xor_sync(0xffffffffu, lsum1, 1);
    lsum1 += __shfl_xor_sync(0xffffffffu, lsum1, 2);
    float inv0 = 1.f / lsum0, inv1 = 1.f / lsum1;

    int b = bh >> 4, h = bh & 15;
    size_t row0 = (size_t)(b*TT + r0g) * CC + h*DD;
    size_t row1 = (size_t)(b*TT + r1g) * CC + h*DD;
#pragma unroll
    for (int j = 0; j < 8; j++) {
        int d = 8*j + t2;
        split_st(g_ah, g_al, row0 + d, oacc[j][0]*inv0, oacc[j][1]*inv0);
        split_st(g_ah, g_al, row1 + d, oacc[j][2]*inv1, oacc[j][3]*inv1);
    }
}

// ---------------------------------------------------------------------------
extern "C" void kernel_launch(void* const* d_in, const int* in_sizes, int n_in,
                              void* d_out, int out_size)
{
    (void)in_sizes; (void)n_in; (void)out_size;
    const float* x  = (const float*)d_in[0];
    const float* Wq = (const float*)d_in[1];
    const float* bq = (const float*)d_in[2];
    const float* Wk = (const float*)d_in[3];
    const float* bk = (const float*)d_in[4];
    const float* Wv = (const float*)d_in[5];
    const float* bv = (const float*)d_in[6];
    const float* Wo = (const float*)d_in[7];
    const float* bo = (const float*)d_in[8];
    float* out = (float*)d_out;

    bf16 *xh, *xl, *ah, *al, *wh, *wl, *qh, *ql, *kh, *kl, *vh, *vl;
    cudaGetSymbolAddress((void**)&xh, g_xh);
    cudaGetSymbolAddress((void**)&xl, g_xl);
    cudaGetSymbolAddress((void**)&ah, g_ah);
    cudaGetSymbolAddress((void**)&al, g_al);
    cudaGetSymbolAddress((void**)&wh, g_wh);
    cudaGetSymbolAddress((void**)&wl, g_wl);
    cudaGetSymbolAddress((void**)&qh, g_qh);
    cudaGetSymbolAddress((void**)&ql, g_ql);
    cudaGetSymbolAddress((void**)&kh, g_kh);
    cudaGetSymbolAddress((void**)&kl, g_kl);
    cudaGetSymbolAddress((void**)&vh, g_vh);
    cudaGetSymbolAddress((void**)&vl, g_vl);

    // 1. split x
    split_kernel<<<(MM*CC/4)/256, 256>>>(x, xh, xl);

    // 2. transpose+split all 4 weights (one launch)
    tsplit_kernel<<<dim3(CC/32, CC/32, 4), dim3(32, 8)>>>(Wq, Wk, Wv, Wo, wh, wl);

    // 3. QKV projections -> split bf16 [B,H,T,D] (Q pre-scaled by 1/8)
    const int gsm = 3 * GSTG;  // 96 KB
    cudaFuncSetAttribute(gemm_bf16x3<0>, cudaFuncAttributeMaxDynamicSharedMemorySize, gsm);
    cudaFuncSetAttribute(gemm_bf16x3<1>, cudaFuncAttributeMaxDynamicSharedMemorySize, gsm);
    dim3 ggrid(CC/128, MM/128);
    gemm_bf16x3<0><<<ggrid, 256, gsm>>>(xh, xl, wh + 0*CC*CC, wl + 0*CC*CC, bq,
                                        nullptr, qh, ql, 0.125f);
    gemm_bf16x3<0><<<ggrid, 256, gsm>>>(xh, xl, wh + 1*CC*CC, wl + 1*CC*CC, bk,
                                        nullptr, kh, kl, 1.0f);
    gemm_bf16x3<0><<<ggrid, 256, gsm>>>(xh, xl, wh + 2*CC*CC, wl + 2*CC*CC, bv,
                                        nullptr, vh, vl, 1.0f);

    // 4. tensor-core flash attention
    const int asm_sz = 98304;
    cudaFuncSetAttribute(attn_mma, cudaFuncAttributeMaxDynamicSharedMemorySize, asm_sz);
    attn_mma<<<dim3(TT/128, BB*HH), 256, asm_sz>>>();

    // 5. output projection -> d_out (fp32)
    gemm_bf16x3<1><<<ggrid, 256, gsm>>>(ah, al, wh + 3*CC*CC, wl + 3*CC*CC, bo,
                                        out, nullptr, nullptr, 1.0f);
}

// round 6
// speedup vs baseline: 1.0031x; 1.0031x over previous
#include <cuda_runtime.h>
#include <cuda_bf16.h>
#include <cstdint>

// B=2, T=2048, C=1024, H=16, D=64, causal MHA, fp32 in/out.
#define BB 2
#define TT 2048
#define CC 1024
#define HH 16
#define DD 64
#define MM (BB*TT)

typedef __nv_bfloat16 bf16;

// ---------------- scratch (allocation-free) ----------------
__device__ bf16 g_xh[MM*CC], g_xl[MM*CC];
__device__ bf16 g_ah[MM*CC], g_al[MM*CC];
__device__ bf16 g_wh[4*CC*CC], g_wl[4*CC*CC];
__device__ bf16 g_qh[BB*HH*TT*DD], g_ql[BB*HH*TT*DD];
__device__ bf16 g_kh[BB*HH*TT*DD], g_kl[BB*HH*TT*DD];
__device__ bf16 g_vh[BB*HH*TT*DD], g_vl[BB*HH*TT*DD];

// ---------------- helpers (sm_80-baseline PTX only) ----------------
__device__ __forceinline__ uint32_t smem_u32(const void* p) {
    return (uint32_t)__cvta_generic_to_shared(p);
}

#define CP16(dst, src) \
    asm volatile("cp.async.cg.shared.global [%0], [%1], 16;" :: "r"(dst), "l"(src) : "memory")
#define CP_COMMIT() asm volatile("cp.async.commit_group;" ::: "memory")
#define CP_WAIT(n)  asm volatile("cp.async.wait_group %0;" :: "n"(n) : "memory")

__device__ __forceinline__ void ldm4(uint32_t* r, uint32_t a) {
    asm volatile("ldmatrix.sync.aligned.m8n8.x4.shared.b16 {%0,%1,%2,%3}, [%4];"
                 : "=r"(r[0]), "=r"(r[1]), "=r"(r[2]), "=r"(r[3]) : "r"(a));
}
__device__ __forceinline__ void ldm4t(uint32_t* r, uint32_t a) {
    asm volatile("ldmatrix.sync.aligned.m8n8.x4.trans.shared.b16 {%0,%1,%2,%3}, [%4];"
                 : "=r"(r[0]), "=r"(r[1]), "=r"(r[2]), "=r"(r[3]) : "r"(a));
}
__device__ __forceinline__ void mma_bf16(float* d, const uint32_t* a, const uint32_t* b) {
    asm volatile("mma.sync.aligned.m16n8k16.row.col.f32.bf16.bf16.f32 "
                 "{%0,%1,%2,%3}, {%4,%5,%6,%7}, {%8,%9}, {%0,%1,%2,%3};"
                 : "+f"(d[0]), "+f"(d[1]), "+f"(d[2]), "+f"(d[3])
                 : "r"(a[0]), "r"(a[1]), "r"(a[2]), "r"(a[3]), "r"(b[0]), "r"(b[1]));
}

__device__ __forceinline__ uint32_t pk2(float a, float b) {
    __nv_bfloat162 t;
    t.x = __float2bfloat16(a); t.y = __float2bfloat16(b);
    return *reinterpret_cast<uint32_t*>(&t);
}
__device__ __forceinline__ void split_st(bf16* hi, bf16* lo, size_t off, float a, float b) {
    bf16 h0 = __float2bfloat16(a), h1 = __float2bfloat16(b);
    *(__nv_bfloat162*)(hi + off) = __nv_bfloat162(h0, h1);
    *(__nv_bfloat162*)(lo + off) =
        __nv_bfloat162(__float2bfloat16(a - __bfloat162float(h0)),
                       __float2bfloat16(b - __bfloat162float(h1)));
}

// ---------------------------------------------------------------------------
__global__ void split_kernel(const float* __restrict__ x,
                             bf16* __restrict__ hi, bf16* __restrict__ lo) {
    int i = blockIdx.x * blockDim.x + threadIdx.x;
    float4 v = ((const float4*)x)[i];
    bf16 h0 = __float2bfloat16(v.x), h1 = __float2bfloat16(v.y);
    bf16 h2 = __float2bfloat16(v.z), h3 = __float2bfloat16(v.w);
    bf16 l0 = __float2bfloat16(v.x - __bfloat162float(h0));
    bf16 l1 = __float2bfloat16(v.y - __bfloat162float(h1));
    bf16 l2 = __float2bfloat16(v.z - __bfloat162float(h2));
    bf16 l3 = __float2bfloat16(v.w - __bfloat162float(h3));
    __nv_bfloat162* hp = (__nv_bfloat162*)(hi + 4*(size_t)i);
    __nv_bfloat162* lp = (__nv_bfloat162*)(lo + 4*(size_t)i);
    hp[0] = __nv_bfloat162(h0, h1); hp[1] = __nv_bfloat162(h2, h3);
    lp[0] = __nv_bfloat162(l0, l1); lp[1] = __nv_bfloat162(l2, l3);
}

// ---------------------------------------------------------------------------
__global__ void tsplit_kernel(const float* __restrict__ W0, const float* __restrict__ W1,
                              const float* __restrict__ W2, const float* __restrict__ W3,
                              bf16* __restrict__ hi, bf16* __restrict__ lo) {
    __shared__ float t[32][33];
    int tx = threadIdx.x, ty = threadIdx.y;          // (32, 8)
    int n0 = blockIdx.x * 32, k0 = blockIdx.y * 32;
    int z = blockIdx.z;
    const float* W = (z == 0) ? W0 : (z == 1) ? W1 : (z == 2) ? W2 : W3;
    bf16* hz = hi + (size_t)z * CC * CC;
    bf16* lz = lo + (size_t)z * CC * CC;
#pragma unroll
    for (int i = 0; i < 4; i++)
        t[ty + 8*i][tx] = W[(size_t)(k0 + ty + 8*i) * CC + n0 + tx];
    __syncthreads();
#pragma unroll
    for (int i = 0; i < 4; i++) {
        float v = t[tx][ty + 8*i];
        bf16 h = __float2bfloat16(v);
        bf16 l = __float2bfloat16(v - __bfloat162float(h));
        size_t o = (size_t)(n0 + ty + 8*i) * CC + k0 + tx;
        hz[o] = h; lz[o] = l;
    }
}

// ---------------------------------------------------------------------------
// mma.sync bf16x3 GEMM, software-pipelined.
// 128x128 tile, K-chunk 64, 3-stage cp.async (192KB), 8 warps (64x32 each).
// Register double-buffered fragments: ldmatrix for kk+1 overlaps mma of kk.
// Smem tile: 128 rows x 64 k, phys(r,c16B) = r*128 + ((c ^ (r&7)) << 4).
// Stage: Ah(16K) Al(16K) Bh(16K) Bl(16K) = 64KB.
// MODE 0: split-bf16 output remapped to [B,H,T,D], scaled. MODE 1: fp32 [M,N].
// ---------------------------------------------------------------------------
#define GSTG 65536
#define NKT  16

template<int MODE>
__global__ __launch_bounds__(256) void gemm_bf16x3(
    const bf16* __restrict__ Ah, const bf16* __restrict__ Al,
    const bf16* __restrict__ Bh, const bf16* __restrict__ Bl,
    const float* __restrict__ bias,
    float* __restrict__ outF, bf16* __restrict__ outH, bf16* __restrict__ outL,
    float scale)
{
    extern __shared__ char smraw[];
    const uint32_t sbase = smem_u32(smraw);

    int tid = threadIdx.x, lane = tid & 31, wid = tid >> 5;
    int wm = wid & 1, wn = wid >> 1;
    int m0 = blockIdx.y << 7, n0 = blockIdx.x << 7;

    float acc[4][4][4] = {};

    auto load_stage = [&](int kt, int s) {
        uint32_t sb = sbase + (uint32_t)s * GSTG;
#pragma unroll
        for (int i = 0; i < 4; i++) {
            int id = tid + i*256;
            int r = id >> 3, c = id & 7;
            uint32_t phys = (uint32_t)(r*128 + ((c ^ (r & 7)) << 4));
            size_t ga = (size_t)(m0 + r)*CC + kt*64 + c*8;
            size_t gb = (size_t)(n0 + r)*CC + kt*64 + c*8;
            CP16(sb +         phys, Ah + ga);
            CP16(sb + 16384 + phys, Al + ga);
            CP16(sb + 32768 + phys, Bh + gb);
            CP16(sb + 49152 + phys, Bl + gb);
        }
        CP_COMMIT();
    };

    load_stage(0, 0);
    load_stage(1, 1);

    int ahalf = lane >> 4;
    int bhalf = (lane >> 3) & 1;
    int arow = wm*64 + (lane & 15);
    int brow = wn*32 + ((lane >> 4) << 3) + (lane & 7);

    // register-double-buffered fragments
    uint32_t Fa[2][4][4], Fal[2][4][4], Fb[2][2][4], Fbl[2][2][4];

#define LDF(B, sb, kk) do {                                                    \
    uint32_t _aswz = (uint32_t)(((2*(kk) + ahalf) ^ (arow & 7)) << 4);         \
    uint32_t _bswz = (uint32_t)(((2*(kk) + bhalf) ^ (brow & 7)) << 4);         \
    _Pragma("unroll")                                                          \
    for (int mf = 0; mf < 4; mf++) {                                           \
        uint32_t off = (uint32_t)((arow + mf*16) * 128) + _aswz;               \
        ldm4(Fa[B][mf], (sb) + off);                                           \
        ldm4(Fal[B][mf], (sb) + 16384 + off);                                  \
    }                                                                          \
    _Pragma("unroll")                                                          \
    for (int nh = 0; nh < 2; nh++) {                                           \
        uint32_t off = (uint32_t)((brow + nh*16) * 128) + _bswz;               \
        ldm4(Fb[B][nh], (sb) + 32768 + off);                                   \
        ldm4(Fbl[B][nh], (sb) + 49152 + off);                                  \
    }                                                                          \
} while (0)

    for (int kt = 0; kt < NKT; kt++) {
        if (kt == NKT - 1) { CP_WAIT(0); } else { CP_WAIT(1); }
        __syncthreads();
        if (kt + 2 < NKT) load_stage(kt + 2, (kt + 2) % 3);

        uint32_t sb = sbase + (uint32_t)(kt % 3) * GSTG;
        LDF(0, sb, 0);
#pragma unroll
        for (int kk = 0; kk < 4; kk++) {
            const int cur = kk & 1;
            if (kk < 3) {
                if (cur) LDF(0, sb, kk + 1); else LDF(1, sb, kk + 1);
            }
#pragma unroll
            for (int mf = 0; mf < 4; mf++)
#pragma unroll
                for (int nf = 0; nf < 4; nf++) {
                    const uint32_t* ph = Fb[cur][nf >> 1] + (nf & 1)*2;
                    const uint32_t* pl = Fbl[cur][nf >> 1] + (nf & 1)*2;
                    mma_bf16(acc[mf][nf], Fa[cur][mf], ph);
                    mma_bf16(acc[mf][nf], Fa[cur][mf], pl);
                    mma_bf16(acc[mf][nf], Fal[cur][mf], ph);
                }
        }
    }
#undef LDF

    int g = lane >> 2, t2 = (lane & 3) * 2;
#pragma unroll
    for (int nf = 0; nf < 4; nf++) {
        int col = n0 + wn*32 + nf*8 + t2;
        float2 bb = *(const float2*)(bias + col);
#pragma unroll
        for (int mf = 0; mf < 4; mf++) {
            int m1 = m0 + wm*64 + mf*16 + g;
            float v0 = acc[mf][nf][0] + bb.x, v1 = acc[mf][nf][1] + bb.y;
            float v2 = acc[mf][nf][2] + bb.x, v3 = acc[mf][nf][3] + bb.y;
            if (MODE == 0) {
                int h = col >> 6, d = col & 63;
                int b1 = m1 >> 11, t1 = m1 & (TT - 1);
                size_t base = ((size_t)(b1*HH + h)*TT) * DD + d;
                split_st(outH, outL, base + (size_t)t1*DD,       v0*scale, v1*scale);
                split_st(outH, outL, base + (size_t)(t1 + 8)*DD, v2*scale, v3*scale);
            } else {
                *(float2*)(outF + (size_t)m1*CC + col)       = make_float2(v0, v1);
                *(float2*)(outF + (size_t)(m1 + 8)*CC + col) = make_float2(v2, v3);
            }
        }
    }
}

// ---------------------------------------------------------------------------
// Tensor-core causal flash attention (bf16x3, fp32 accum). Unchanged (R4).
// ---------------------------------------------------------------------------
__global__ __launch_bounds__(256) void attn_mma()
{
    extern __shared__ char smraw[];
    const uint32_t sb = smem_u32(smraw);
    const uint32_t QH = 0, QL = 16384, ST = 32768, STSZ = 32768;

    int tid = threadIdx.x, lane = tid & 31, w = tid >> 5;
    int bh = blockIdx.y;
    int qt = (int)gridDim.x - 1 - (int)blockIdx.x;
    int q0 = qt * 128;
    int nkt = 2*qt + 2;

    const bf16* Qh = g_qh + (size_t)bh*TT*DD;
    const bf16* Ql = g_ql + (size_t)bh*TT*DD;
    const bf16* Kh = g_kh + (size_t)bh*TT*DD;
    const bf16* Kl = g_kl + (size_t)bh*TT*DD;
    const bf16* Vh = g_vh + (size_t)bh*TT*DD;
    const bf16* Vl = g_vl + (size_t)bh*TT*DD;

    auto load_kv = [&](int kt, int s) {
        uint32_t base = sb + ST + (uint32_t)s * STSZ;
        int k0 = kt * 64;
#pragma unroll
        for (int i = 0; i < 2; i++) {
            int id = tid + i*256;
            int r = id >> 3, c = id & 7;
            uint32_t phys = (uint32_t)(r*128 + ((c ^ (r & 7)) << 4));
            size_t gsrc = (size_t)(k0 + r)*DD + c*8;
            CP16(base +         phys, Kh + gsrc);
            CP16(base +  8192 + phys, Kl + gsrc);
            CP16(base + 16384 + phys, Vh + gsrc);
            CP16(base + 24576 + phys, Vl + gsrc);
        }
        CP_COMMIT();
    };

#pragma unroll
    for (int m = 0; m < 2; m++)
#pragma unroll
        for (int i = 0; i < 4; i++) {
            int id = tid + i*256;
            int r = id >> 3, c = id & 7;
            uint32_t dst = sb + (m ? QL : QH) + (uint32_t)(r*128 + ((c ^ (r & 7)) << 4));
            const bf16* src = (m ? Ql : Qh) + (size_t)(q0 + r)*DD + c*8;
            CP16(dst, src);
        }
    CP_COMMIT();
    load_kv(0, 0);

    CP_WAIT(1);
    __syncthreads();

    uint32_t qfh[4][4], qfl[4][4];
    int arow = w*16 + (lane & 15), ahalf = lane >> 4;
#pragma unroll
    for (int kk = 0; kk < 4; kk++) {
        uint32_t off = (uint32_t)(arow*128 + (((2*kk + ahalf) ^ (arow & 7)) << 4));
        ldm4(qfh[kk], sb + QH + off);
        ldm4(qfl[kk], sb + QL + off);
    }

    float oacc[8][4] = {};
    float mrow0 = -1e30f, mrow1 = -1e30f;
    float lsum0 = 0.f, lsum1 = 0.f;

    int g = lane >> 2, t2 = (lane & 3) * 2;
    int r0g = q0 + 16*w + g, r1g = r0g + 8;
    int bhalf = (lane >> 3) & 1;
    int vi = lane >> 3, vr = lane & 7;

    for (int kt = 0; kt < nkt; kt++) {
        if (kt + 1 < nkt) { load_kv(kt + 1, (kt + 1) & 1); CP_WAIT(1); }
        else              { CP_WAIT(0); }
        __syncthreads();

        int k0 = kt * 64;
        if (k0 <= q0 + 16*w + 15) {
            uint32_t st = sb + ST + (uint32_t)(kt & 1) * STSZ;

            float sacc[8][4] = {};
#pragma unroll
            for (int kk = 0; kk < 4; kk++) {
#pragma unroll
                for (int ng = 0; ng < 4; ng++) {
                    int brow = ng*16 + ((lane >> 4) << 3) + (lane & 7);
                    uint32_t off = (uint32_t)(brow*128 + (((2*kk + bhalf) ^ (brow & 7)) << 4));
                    uint32_t kh4[4], kl4[4];
                    ldm4(kh4, st + off);
                    ldm4(kl4, st + 8192 + off);
                    mma_bf16(sacc[2*ng],   qfh[kk], kh4);
                    mma_bf16(sacc[2*ng],   qfh[kk], kl4);
                    mma_bf16(sacc[2*ng],   qfl[kk], kh4);
                    mma_bf16(sacc[2*ng+1], qfh[kk], kh4 + 2);
                    mma_bf16(sacc[2*ng+1], qfh[kk], kl4 + 2);
                    mma_bf16(sacc[2*ng+1], qfl[kk], kh4 + 2);
                }
            }

            if (k0 + 63 > r0g) {
#pragma unroll
                for (int j = 0; j < 8; j++) {
                    int col = k0 + 8*j + t2;
                    if (col     > r0g) sacc[j][0] = -1e30f;
                    if (col + 1 > r0g) sacc[j][1] = -1e30f;
                    if (col     > r1g) sacc[j][2] = -1e30f;
                    if (col + 1 > r1g) sacc[j][3] = -1e30f;
                }
            }

            float tm0 = -1e30f, tm1 = -1e30f;
#pragma unroll
            for (int j = 0; j < 8; j++) {
                tm0 = fmaxf(tm0, fmaxf(sacc[j][0], sacc[j][1]));
                tm1 = fmaxf(tm1, fmaxf(sacc[j][2], sacc[j][3]));
            }
            tm0 = fmaxf(tm0, __shfl_xor_sync(0xffffffffu, tm0, 1));
            tm0 = fmaxf(tm0, __shfl_xor_sync(0xffffffffu, tm0, 2));
            tm1 = fmaxf(tm1, __shfl_xor_sync(0xffffffffu, tm1, 1));
            tm1 = fmaxf(tm1, __shfl_xor_sync(0xffffffffu, tm1, 2));
            float mn0 = fmaxf(mrow0, tm0), mn1 = fmaxf(mrow1, tm1);
            float c0 = __expf(mrow0 - mn0), c1 = __expf(mrow1 - mn1);
            mrow0 = mn0; mrow1 = mn1;

            float ps0 = 0.f, ps1 = 0.f;
            uint32_t pfh[4][4], pfl[4][4];
#pragma unroll
            for (int kc = 0; kc < 4; kc++) {
#pragma unroll
                for (int jj = 0; jj < 2; jj++) {
                    int j = 2*kc + jj;
                    float p0 = __expf(sacc[j][0] - mn0);
                    float p1 = __expf(sacc[j][1] - mn0);
                    float p2 = __expf(sacc[j][2] - mn1);
                    float p3 = __expf(sacc[j][3] - mn1);
                    ps0 += p0 + p1; ps1 += p2 + p3;
                    float h0 = __bfloat162float(__float2bfloat16(p0));
                    float h1 = __bfloat162float(__float2bfloat16(p1));
                    float h2 = __bfloat162float(__float2bfloat16(p2));
                    float h3 = __bfloat162float(__float2bfloat16(p3));
                    pfh[kc][2*jj]   = pk2(h0, h1);
                    pfh[kc][2*jj+1] = pk2(h2, h3);
                    pfl[kc][2*jj]   = pk2(p0 - h0, p1 - h1);
                    pfl[kc][2*jj+1] = pk2(p2 - h2, p3 - h3);
                }
            }
            lsum0 = lsum0 * c0 + ps0;
            lsum1 = lsum1 * c1 + ps1;
#pragma unroll
            for (int j = 0; j < 8; j++) {
                oacc[j][0] *= c0; oacc[j][1] *= c0;
                oacc[j][2] *= c1; oacc[j][3] *= c1;
            }

#pragma unroll
            for (int kc = 0; kc < 4; kc++) {
#pragma unroll
                for (int dg = 0; dg < 4; dg++) {
                    int key = kc*16 + 8*(vi & 1) + vr;
                    int dc = 2*dg + (vi >> 1);
                    uint32_t off = (uint32_t)(key*128 + ((dc ^ (key & 7)) << 4));
                    uint32_t vh4[4], vl4[4];
                    ldm4t(vh4, st + 16384 + off);
                    ldm4t(vl4, st + 24576 + off);
                    mma_bf16(oacc[2*dg],   pfh[kc], vh4);
                    mma_bf16(oacc[2*dg],   pfh[kc], vl4);
                    mma_bf16(oacc[2*dg],   pfl[kc], vh4);
                    mma_bf16(oacc[2*dg+1], pfh[kc], vh4 + 2);
                    mma_bf16(oacc[2*dg+1], pfh[kc], vl4 + 2);
                    mma_bf16(oacc[2*dg+1], pfl[kc], vh4 + 2);
                }
            }
        }
        __syncthreads();
    }

    lsum0 += __shfl_xor_sync(0xffffffffu, lsum0, 1);
    lsum0 += __shfl_xor_sync(0xffffffffu, lsum0, 2);
    lsum1 += __shfl_xor_sync(0xffffffffu, lsum1, 1);
    lsum1 += __shfl_xor_sync(0xffffffffu, lsum1, 2);
    float inv0 = 1.f / lsum0, inv1 = 1.f / lsum1;

    int b = bh >> 4, h = bh & 15;
    size_t row0 = (size_t)(b*TT + r0g) * CC + h*DD;
    size_t row1 = (size_t)(b*TT + r1g) * CC + h*DD;
#pragma unroll
    for (int j = 0; j < 8; j++) {
        int d = 8*j + t2;
        split_st(g_ah, g_al, row0 + d, oacc[j][0]*inv0, oacc[j][1]*inv0);
        split_st(g_ah, g_al, row1 + d, oacc[j][2]*inv1, oacc[j][3]*inv1);
    }
}

// ---------------------------------------------------------------------------
extern "C" void kernel_launch(void* const* d_in, const int* in_sizes, int n_in,
                              void* d_out, int out_size)
{
    (void)in_sizes; (void)n_in; (void)out_size;
    const float* x  = (const float*)d_in[0];
    const float* Wq = (const float*)d_in[1];
    const float* bq = (const float*)d_in[2];
    const float* Wk = (const float*)d_in[3];
    const float* bk = (const float*)d_in[4];
    const float* Wv = (const float*)d_in[5];
    const float* bv = (const float*)d_in[6];
    const float* Wo = (const float*)d_in[7];
    const float* bo = (const float*)d_in[8];
    float* out = (float*)d_out;

    bf16 *xh, *xl, *ah, *al, *wh, *wl, *qh, *ql, *kh, *kl, *vh, *vl;
    cudaGetSymbolAddress((void**)&xh, g_xh);
    cudaGetSymbolAddress((void**)&xl, g_xl);
    cudaGetSymbolAddress((void**)&ah, g_ah);
    cudaGetSymbolAddress((void**)&al, g_al);
    cudaGetSymbolAddress((void**)&wh, g_wh);
    cudaGetSymbolAddress((void**)&wl, g_wl);
    cudaGetSymbolAddress((void**)&qh, g_qh);
    cudaGetSymbolAddress((void**)&ql, g_ql);
    cudaGetSymbolAddress((void**)&kh, g_kh);
    cudaGetSymbolAddress((void**)&kl, g_kl);
    cudaGetSymbolAddress((void**)&vh, g_vh);
    cudaGetSymbolAddress((void**)&vl, g_vl);

    // 1. split x
    split_kernel<<<(MM*CC/4)/256, 256>>>(x, xh, xl);

    // 2. transpose+split all 4 weights (one launch)
    tsplit_kernel<<<dim3(CC/32, CC/32, 4), dim3(32, 8)>>>(Wq, Wk, Wv, Wo, wh, wl);

    // 3. QKV projections -> split bf16 [B,H,T,D] (Q pre-scaled by 1/8)
    const int gsm = 3 * GSTG;  // 192 KB
    cudaFuncSetAttribute(gemm_bf16x3<0>, cudaFuncAttributeMaxDynamicSharedMemorySize, gsm);
    cudaFuncSetAttribute(gemm_bf16x3<1>, cudaFuncAttributeMaxDynamicSharedMemorySize, gsm);
    dim3 ggrid(CC/128, MM/128);
    gemm_bf16x3<0><<<ggrid, 256, gsm>>>(xh, xl, wh + 0*CC*CC, wl + 0*CC*CC, bq,
                                        nullptr, qh, ql, 0.125f);
    gemm_bf16x3<0><<<ggrid, 256, gsm>>>(xh, xl, wh + 1*CC*CC, wl + 1*CC*CC, bk,
                                        nullptr, kh, kl, 1.0f);
    gemm_bf16x3<0><<<ggrid, 256, gsm>>>(xh, xl, wh + 2*CC*CC, wl + 2*CC*CC, bv,
                                        nullptr, vh, vl, 1.0f);

    // 4. tensor-core flash attention
    const int asm_sz = 98304;
    cudaFuncSetAttribute(attn_mma, cudaFuncAttributeMaxDynamicSharedMemorySize, asm_sz);
    attn_mma<<<dim3(TT/128, BB*HH), 256, asm_sz>>>();

    // 5. output projection -> d_out (fp32)
    gemm_bf16x3<1><<<ggrid, 256, gsm>>>(ah, al, wh + 3*CC*CC, wl + 3*CC*CC, bo,
                                        out, nullptr, nullptr, 1.0f);
}

// round 7
// speedup vs baseline: 1.0299x; 1.0266x over previous
#include <cuda_runtime.h>
#include <cuda_bf16.h>
#include <cstdint>

// B=2, T=2048, C=1024, H=16, D=64, causal MHA, fp32 in/out.
#define BB 2
#define TT 2048
#define CC 1024
#define HH 16
#define DD 64
#define MM (BB*TT)

typedef __nv_bfloat16 bf16;

// ---------------- scratch (allocation-free) ----------------
__device__ bf16 g_xh[MM*CC], g_xl[MM*CC];
__device__ bf16 g_ah[MM*CC], g_al[MM*CC];
__device__ bf16 g_wh[4*CC*CC], g_wl[4*CC*CC];
__device__ bf16 g_qh[BB*HH*TT*DD], g_ql[BB*HH*TT*DD];
__device__ bf16 g_kh[BB*HH*TT*DD], g_kl[BB*HH*TT*DD];
__device__ bf16 g_vh[BB*HH*TT*DD], g_vl[BB*HH*TT*DD];

// ---------------- helpers (sm_80-baseline PTX only) ----------------
__device__ __forceinline__ uint32_t smem_u32(const void* p) {
    return (uint32_t)__cvta_generic_to_shared(p);
}

#define CP16(dst, src) \
    asm volatile("cp.async.cg.shared.global [%0], [%1], 16;" :: "r"(dst), "l"(src) : "memory")
#define CP_COMMIT() asm volatile("cp.async.commit_group;" ::: "memory")
#define CP_WAIT(n)  asm volatile("cp.async.wait_group %0;" :: "n"(n) : "memory")

__device__ __forceinline__ void ldm4(uint32_t* r, uint32_t a) {
    asm volatile("ldmatrix.sync.aligned.m8n8.x4.shared.b16 {%0,%1,%2,%3}, [%4];"
                 : "=r"(r[0]), "=r"(r[1]), "=r"(r[2]), "=r"(r[3]) : "r"(a));
}
__device__ __forceinline__ void ldm4t(uint32_t* r, uint32_t a) {
    asm volatile("ldmatrix.sync.aligned.m8n8.x4.trans.shared.b16 {%0,%1,%2,%3}, [%4];"
                 : "=r"(r[0]), "=r"(r[1]), "=r"(r[2]), "=r"(r[3]) : "r"(a));
}
__device__ __forceinline__ void mma_bf16(float* d, const uint32_t* a, const uint32_t* b) {
    asm volatile("mma.sync.aligned.m16n8k16.row.col.f32.bf16.bf16.f32 "
                 "{%0,%1,%2,%3}, {%4,%5,%6,%7}, {%8,%9}, {%0,%1,%2,%3};"
                 : "+f"(d[0]), "+f"(d[1]), "+f"(d[2]), "+f"(d[3])
                 : "r"(a[0]), "r"(a[1]), "r"(a[2]), "r"(a[3]), "r"(b[0]), "r"(b[1]));
}

__device__ __forceinline__ uint32_t pk2(float a, float b) {
    __nv_bfloat162 t;
    t.x = __float2bfloat16(a); t.y = __float2bfloat16(b);
    return *reinterpret_cast<uint32_t*>(&t);
}
__device__ __forceinline__ void split_st(bf16* hi, bf16* lo, size_t off, float a, float b) {
    bf16 h0 = __float2bfloat16(a), h1 = __float2bfloat16(b);
    *(__nv_bfloat162*)(hi + off) = __nv_bfloat162(h0, h1);
    *(__nv_bfloat162*)(lo + off) =
        __nv_bfloat162(__float2bfloat16(a - __bfloat162float(h0)),
                       __float2bfloat16(b - __bfloat162float(h1)));
}

// ---------------------------------------------------------------------------
__global__ void split_kernel(const float* __restrict__ x,
                             bf16* __restrict__ hi, bf16* __restrict__ lo) {
    int i = blockIdx.x * blockDim.x + threadIdx.x;
    float4 v = ((const float4*)x)[i];
    bf16 h0 = __float2bfloat16(v.x), h1 = __float2bfloat16(v.y);
    bf16 h2 = __float2bfloat16(v.z), h3 = __float2bfloat16(v.w);
    bf16 l0 = __float2bfloat16(v.x - __bfloat162float(h0));
    bf16 l1 = __float2bfloat16(v.y - __bfloat162float(h1));
    bf16 l2 = __float2bfloat16(v.z - __bfloat162float(h2));
    bf16 l3 = __float2bfloat16(v.w - __bfloat162float(h3));
    __nv_bfloat162* hp = (__nv_bfloat162*)(hi + 4*(size_t)i);
    __nv_bfloat162* lp = (__nv_bfloat162*)(lo + 4*(size_t)i);
    hp[0] = __nv_bfloat162(h0, h1); hp[1] = __nv_bfloat162(h2, h3);
    lp[0] = __nv_bfloat162(l0, l1); lp[1] = __nv_bfloat162(l2, l3);
}

// ---------------------------------------------------------------------------
__global__ void tsplit_kernel(const float* __restrict__ W0, const float* __restrict__ W1,
                              const float* __restrict__ W2, const float* __restrict__ W3,
                              bf16* __restrict__ hi, bf16* __restrict__ lo) {
    __shared__ float t[32][33];
    int tx = threadIdx.x, ty = threadIdx.y;          // (32, 8)
    int n0 = blockIdx.x * 32, k0 = blockIdx.y * 32;
    int z = blockIdx.z;
    const float* W = (z == 0) ? W0 : (z == 1) ? W1 : (z == 2) ? W2 : W3;
    bf16* hz = hi + (size_t)z * CC * CC;
    bf16* lz = lo + (size_t)z * CC * CC;
#pragma unroll
    for (int i = 0; i < 4; i++)
        t[ty + 8*i][tx] = W[(size_t)(k0 + ty + 8*i) * CC + n0 + tx];
    __syncthreads();
#pragma unroll
    for (int i = 0; i < 4; i++) {
        float v = t[tx][ty + 8*i];
        bf16 h = __float2bfloat16(v);
        bf16 l = __float2bfloat16(v - __bfloat162float(h));
        size_t o = (size_t)(n0 + ty + 8*i) * CC + k0 + tx;
        hz[o] = h; lz[o] = l;
    }
}

// ---------------------------------------------------------------------------
// mma.sync bf16x3 GEMM, wide warp tile.
// Block 128x256, warp tile 64x64 (2m x 4n warps), K-chunk 64, 2-stage cp.async.
// Per kk-step per warp: 96 MMA vs 16 LDSM (double the R6 ratio).
// Stage: Ah(16K) Al(16K) Bh(32K) Bl(32K) = 96KB; 2 stages = 192KB, occ 1.
// Smem tile phys(r, c16B) = r*128 + ((c ^ (r&7)) << 4), conflict-free ldmatrix.
// MODE 0: split-bf16 output remapped to [B,H,T,D], scaled. MODE 1: fp32 [M,N].
// ---------------------------------------------------------------------------
#define GSTG 98304
#define NKT  16

template<int MODE>
__global__ __launch_bounds__(256) void gemm_bf16x3(
    const bf16* __restrict__ Ah, const bf16* __restrict__ Al,
    const bf16* __restrict__ Bh, const bf16* __restrict__ Bl,
    const float* __restrict__ bias,
    float* __restrict__ outF, bf16* __restrict__ outH, bf16* __restrict__ outL,
    float scale)
{
    extern __shared__ char smraw[];
    const uint32_t sbase = smem_u32(smraw);

    int tid = threadIdx.x, lane = tid & 31, wid = tid >> 5;
    int wm = wid & 1, wn = wid >> 1;                  // 2 x 4 warps, 64x64 each
    int m0 = blockIdx.y << 7, n0 = blockIdx.x << 8;   // 128 x 256 block

    float acc[4][8][4] = {};

    auto load_stage = [&](int kt, int s) {
        uint32_t sb = sbase + (uint32_t)s * GSTG;
#pragma unroll
        for (int i = 0; i < 4; i++) {                 // A: 128 rows
            int id = tid + i*256;
            int r = id >> 3, c = id & 7;
            uint32_t phys = (uint32_t)(r*128 + ((c ^ (r & 7)) << 4));
            size_t ga = (size_t)(m0 + r)*CC + kt*64 + c*8;
            CP16(sb +         phys, Ah + ga);
            CP16(sb + 16384 + phys, Al + ga);
        }
#pragma unroll
        for (int i = 0; i < 8; i++) {                 // B: 256 rows
            int id = tid + i*256;
            int r = id >> 3, c = id & 7;
            uint32_t phys = (uint32_t)(r*128 + ((c ^ (r & 7)) << 4));
            size_t gb = (size_t)(n0 + r)*CC + kt*64 + c*8;
            CP16(sb + 32768 + phys, Bh + gb);
            CP16(sb + 65536 + phys, Bl + gb);
        }
        CP_COMMIT();
    };

    load_stage(0, 0);

    int ahalf = lane >> 4;
    int bhalf = (lane >> 3) & 1;
    int arow = wm*64 + (lane & 15);
    int browb = wn*64 + ((lane >> 4) << 3) + (lane & 7);

    for (int kt = 0; kt < NKT; kt++) {
        if (kt + 1 < NKT) { load_stage(kt + 1, (kt + 1) & 1); CP_WAIT(1); }
        else              { CP_WAIT(0); }
        __syncthreads();

        uint32_t sb = sbase + (uint32_t)(kt & 1) * GSTG;
#pragma unroll
        for (int kk = 0; kk < 4; kk++) {
            uint32_t aswz = (uint32_t)(((2*kk + ahalf) ^ (arow & 7)) << 4);
            uint32_t bswz = (uint32_t)(((2*kk + bhalf) ^ (browb & 7)) << 4);
            uint32_t ah4[4][4], al4[4][4];
#pragma unroll
            for (int mf = 0; mf < 4; mf++) {
                uint32_t off = (uint32_t)((arow + mf*16) * 128) + aswz;
                ldm4(ah4[mf], sb + off);
                ldm4(al4[mf], sb + 16384 + off);
            }
#pragma unroll
            for (int nhh = 0; nhh < 2; nhh++) {       // two 32-col halves
                uint32_t bh4[2][4], bl4[2][4];
#pragma unroll
                for (int nh2 = 0; nh2 < 2; nh2++) {
                    uint32_t off = (uint32_t)((browb + (nhh*2 + nh2)*16) * 128) + bswz;
                    ldm4(bh4[nh2], sb + 32768 + off);
                    ldm4(bl4[nh2], sb + 65536 + off);
                }
#pragma unroll
                for (int mf = 0; mf < 4; mf++)
#pragma unroll
                    for (int nf2 = 0; nf2 < 4; nf2++) {
                        const uint32_t* ph = bh4[nf2 >> 1] + (nf2 & 1)*2;
                        const uint32_t* pl = bl4[nf2 >> 1] + (nf2 & 1)*2;
                        float* a = acc[mf][nhh*4 + nf2];
                        mma_bf16(a, ah4[mf], ph);
                        mma_bf16(a, ah4[mf], pl);
                        mma_bf16(a, al4[mf], ph);
                    }
            }
        }
        __syncthreads();
    }

    int g = lane >> 2, t2 = (lane & 3) * 2;
#pragma unroll
    for (int nf = 0; nf < 8; nf++) {
        int col = n0 + wn*64 + nf*8 + t2;
        float2 bb = *(const float2*)(bias + col);
#pragma unroll
        for (int mf = 0; mf < 4; mf++) {
            int m1 = m0 + wm*64 + mf*16 + g;
            float v0 = acc[mf][nf][0] + bb.x, v1 = acc[mf][nf][1] + bb.y;
            float v2 = acc[mf][nf][2] + bb.x, v3 = acc[mf][nf][3] + bb.y;
            if (MODE == 0) {
                int h = col >> 6, d = col & 63;
                int b1 = m1 >> 11, t1 = m1 & (TT - 1);
                size_t base = ((size_t)(b1*HH + h)*TT) * DD + d;
                split_st(outH, outL, base + (size_t)t1*DD,       v0*scale, v1*scale);
                split_st(outH, outL, base + (size_t)(t1 + 8)*DD, v2*scale, v3*scale);
            } else {
                *(float2*)(outF + (size_t)m1*CC + col)       = make_float2(v0, v1);
                *(float2*)(outF + (size_t)(m1 + 8)*CC + col) = make_float2(v2, v3);
            }
        }
    }
}

// ---------------------------------------------------------------------------
// Tensor-core causal flash attention (bf16x3, fp32 accum). Unchanged (R4).
// ---------------------------------------------------------------------------
__global__ __launch_bounds__(256) void attn_mma()
{
    extern __shared__ char smraw[];
    const uint32_t sb = smem_u32(smraw);
    const uint32_t QH = 0, QL = 16384, ST = 32768, STSZ = 32768;

    int tid = threadIdx.x, lane = tid & 31, w = tid >> 5;
    int bh = blockIdx.y;
    int qt = (int)gridDim.x - 1 - (int)blockIdx.x;
    int q0 = qt * 128;
    int nkt = 2*qt + 2;

    const bf16* Qh = g_qh + (size_t)bh*TT*DD;
    const bf16* Ql = g_ql + (size_t)bh*TT*DD;
    const bf16* Kh = g_kh + (size_t)bh*TT*DD;
    const bf16* Kl = g_kl + (size_t)bh*TT*DD;
    const bf16* Vh = g_vh + (size_t)bh*TT*DD;
    const bf16* Vl = g_vl + (size_t)bh*TT*DD;

    auto load_kv = [&](int kt, int s) {
        uint32_t base = sb + ST + (uint32_t)s * STSZ;
        int k0 = kt * 64;
#pragma unroll
        for (int i = 0; i < 2; i++) {
            int id = tid + i*256;
            int r = id >> 3, c = id & 7;
            uint32_t phys = (uint32_t)(r*128 + ((c ^ (r & 7)) << 4));
            size_t gsrc = (size_t)(k0 + r)*DD + c*8;
            CP16(base +         phys, Kh + gsrc);
            CP16(base +  8192 + phys, Kl + gsrc);
            CP16(base + 16384 + phys, Vh + gsrc);
            CP16(base + 24576 + phys, Vl + gsrc);
        }
        CP_COMMIT();
    };

#pragma unroll
    for (int m = 0; m < 2; m++)
#pragma unroll
        for (int i = 0; i < 4; i++) {
            int id = tid + i*256;
            int r = id >> 3, c = id & 7;
            uint32_t dst = sb + (m ? QL : QH) + (uint32_t)(r*128 + ((c ^ (r & 7)) << 4));
            const bf16* src = (m ? Ql : Qh) + (size_t)(q0 + r)*DD + c*8;
            CP16(dst, src);
        }
    CP_COMMIT();
    load_kv(0, 0);

    CP_WAIT(1);
    __syncthreads();

    uint32_t qfh[4][4], qfl[4][4];
    int arow = w*16 + (lane & 15), ahalf = lane >> 4;
#pragma unroll
    for (int kk = 0; kk < 4; kk++) {
        uint32_t off = (uint32_t)(arow*128 + (((2*kk + ahalf) ^ (arow & 7)) << 4));
        ldm4(qfh[kk], sb + QH + off);
        ldm4(qfl[kk], sb + QL + off);
    }

    float oacc[8][4] = {};
    float mrow0 = -1e30f, mrow1 = -1e30f;
    float lsum0 = 0.f, lsum1 = 0.f;

    int g = lane >> 2, t2 = (lane & 3) * 2;
    int r0g = q0 + 16*w + g, r1g = r0g + 8;
    int bhalf = (lane >> 3) & 1;
    int vi = lane >> 3, vr = lane & 7;

    for (int kt = 0; kt < nkt; kt++) {
        if (kt + 1 < nkt) { load_kv(kt + 1, (kt + 1) & 1); CP_WAIT(1); }
        else              { CP_WAIT(0); }
        __syncthreads();

        int k0 = kt * 64;
        if (k0 <= q0 + 16*w + 15) {
            uint32_t st = sb + ST + (uint32_t)(kt & 1) * STSZ;

            float sacc[8][4] = {};
#pragma unroll
            for (int kk = 0; kk < 4; kk++) {
#pragma unroll
                for (int ng = 0; ng < 4; ng++) {
                    int brow = ng*16 + ((lane >> 4) << 3) + (lane & 7);
                    uint32_t off = (uint32_t)(brow*128 + (((2*kk + bhalf) ^ (brow & 7)) << 4));
                    uint32_t kh4[4], kl4[4];
                    ldm4(kh4, st + off);
                    ldm4(kl4, st + 8192 + off);
                    mma_bf16(sacc[2*ng],   qfh[kk], kh4);
                    mma_bf16(sacc[2*ng],   qfh[kk], kl4);
                    mma_bf16(sacc[2*ng],   qfl[kk], kh4);
                    mma_bf16(sacc[2*ng+1], qfh[kk], kh4 + 2);
                    mma_bf16(sacc[2*ng+1], qfh[kk], kl4 + 2);
                    mma_bf16(sacc[2*ng+1], qfl[kk], kh4 + 2);
                }
            }

            if (k0 + 63 > r0g) {
#pragma unroll
                for (int j = 0; j < 8; j++) {
                    int col = k0 + 8*j + t2;
                    if (col     > r0g) sacc[j][0] = -1e30f;
                    if (col + 1 > r0g) sacc[j][1] = -1e30f;
                    if (col     > r1g) sacc[j][2] = -1e30f;
                    if (col + 1 > r1g) sacc[j][3] = -1e30f;
                }
            }

            float tm0 = -1e30f, tm1 = -1e30f;
#pragma unroll
            for (int j = 0; j < 8; j++) {
                tm0 = fmaxf(tm0, fmaxf(sacc[j][0], sacc[j][1]));
                tm1 = fmaxf(tm1, fmaxf(sacc[j][2], sacc[j][3]));
            }
            tm0 = fmaxf(tm0, __shfl_xor_sync(0xffffffffu, tm0, 1));
            tm0 = fmaxf(tm0, __shfl_xor_sync(0xffffffffu, tm0, 2));
            tm1 = fmaxf(tm1, __shfl_xor_sync(0xffffffffu, tm1, 1));
            tm1 = fmaxf(tm1, __shfl_xor_sync(0xffffffffu, tm1, 2));
            float mn0 = fmaxf(mrow0, tm0), mn1 = fmaxf(mrow1, tm1);
            float c0 = __expf(mrow0 - mn0), c1 = __expf(mrow1 - mn1);
            mrow0 = mn0; mrow1 = mn1;

            float ps0 = 0.f, ps1 = 0.f;
            uint32_t pfh[4][4], pfl[4][4];
#pragma unroll
            for (int kc = 0; kc < 4; kc++) {
#pragma unroll
                for (int jj = 0; jj < 2; jj++) {
                    int j = 2*kc + jj;
                    float p0 = __expf(sacc[j][0] - mn0);
                    float p1 = __expf(sacc[j][1] - mn0);
                    float p2 = __expf(sacc[j][2] - mn1);
                    float p3 = __expf(sacc[j][3] - mn1);
                    ps0 += p0 + p1; ps1 += p2 + p3;
                    float h0 = __bfloat162float(__float2bfloat16(p0));
                    float h1 = __bfloat162float(__float2bfloat16(p1));
                    float h2 = __bfloat162float(__float2bfloat16(p2));
                    float h3 = __bfloat162float(__float2bfloat16(p3));
                    pfh[kc][2*jj]   = pk2(h0, h1);
                    pfh[kc][2*jj+1] = pk2(h2, h3);
                    pfl[kc][2*jj]   = pk2(p0 - h0, p1 - h1);
                    pfl[kc][2*jj+1] = pk2(p2 - h2, p3 - h3);
                }
            }
            lsum0 = lsum0 * c0 + ps0;
            lsum1 = lsum1 * c1 + ps1;
#pragma unroll
            for (int j = 0; j < 8; j++) {
                oacc[j][0] *= c0; oacc[j][1] *= c0;
                oacc[j][2] *= c1; oacc[j][3] *= c1;
            }

#pragma unroll
            for (int kc = 0; kc < 4; kc++) {
#pragma unroll
                for (int dg = 0; dg < 4; dg++) {
                    int key = kc*16 + 8*(vi & 1) + vr;
                    int dc = 2*dg + (vi >> 1);
                    uint32_t off = (uint32_t)(key*128 + ((dc ^ (key & 7)) << 4));
                    uint32_t vh4[4], vl4[4];
                    ldm4t(vh4, st + 16384 + off);
                    ldm4t(vl4, st + 24576 + off);
                    mma_bf16(oacc[2*dg],   pfh[kc], vh4);
                    mma_bf16(oacc[2*dg],   pfh[kc], vl4);
                    mma_bf16(oacc[2*dg],   pfl[kc], vh4);
                    mma_bf16(oacc[2*dg+1], pfh[kc], vh4 + 2);
                    mma_bf16(oacc[2*dg+1], pfh[kc], vl4 + 2);
                    mma_bf16(oacc[2*dg+1], pfl[kc], vh4 + 2);
                }
            }
        }
        __syncthreads();
    }

    lsum0 += __shfl_xor_sync(0xffffffffu, lsum0, 1);
    lsum0 += __shfl_xor_sync(0xffffffffu, lsum0, 2);
    lsum1 += __shfl_xor_sync(0xffffffffu, lsum1, 1);
    lsum1 += __shfl_xor_sync(0xffffffffu, lsum1, 2);
    float inv0 = 1.f / lsum0, inv1 = 1.f / lsum1;

    int b = bh >> 4, h = bh & 15;
    size_t row0 = (size_t)(b*TT + r0g) * CC + h*DD;
    size_t row1 = (size_t)(b*TT + r1g) * CC + h*DD;
#pragma unroll
    for (int j = 0; j < 8; j++) {
        int d = 8*j + t2;
        split_st(g_ah, g_al, row0 + d, oacc[j][0]*inv0, oacc[j][1]*inv0);
        split_st(g_ah, g_al, row1 + d, oacc[j][2]*inv1, oacc[j][3]*inv1);
    }
}

// ---------------------------------------------------------------------------
extern "C" void kernel_launch(void* const* d_in, const int* in_sizes, int n_in,
                              void* d_out, int out_size)
{
    (void)in_sizes; (void)n_in; (void)out_size;
    const float* x  = (const float*)d_in[0];
    const float* Wq = (const float*)d_in[1];
    const float* bq = (const float*)d_in[2];
    const float* Wk = (const float*)d_in[3];
    const float* bk = (const float*)d_in[4];
    const float* Wv = (const float*)d_in[5];
    const float* bv = (const float*)d_in[6];
    const float* Wo = (const float*)d_in[7];
    const float* bo = (const float*)d_in[8];
    float* out = (float*)d_out;

    bf16 *xh, *xl, *ah, *al, *wh, *wl, *qh, *ql, *kh, *kl, *vh, *vl;
    cudaGetSymbolAddress((void**)&xh, g_xh);
    cudaGetSymbolAddress((void**)&xl, g_xl);
    cudaGetSymbolAddress((void**)&ah, g_ah);
    cudaGetSymbolAddress((void**)&al, g_al);
    cudaGetSymbolAddress((void**)&wh, g_wh);
    cudaGetSymbolAddress((void**)&wl, g_wl);
    cudaGetSymbolAddress((void**)&qh, g_qh);
    cudaGetSymbolAddress((void**)&ql, g_ql);
    cudaGetSymbolAddress((void**)&kh, g_kh);
    cudaGetSymbolAddress((void**)&kl, g_kl);
    cudaGetSymbolAddress((void**)&vh, g_vh);
    cudaGetSymbolAddress((void**)&vl, g_vl);

    // 1. split x
    split_kernel<<<(MM*CC/4)/256, 256>>>(x, xh, xl);

    // 2. transpose+split all 4 weights (one launch)
    tsplit_kernel<<<dim3(CC/32, CC/32, 4), dim3(32, 8)>>>(Wq, Wk, Wv, Wo, wh, wl);

    // 3. QKV projections -> split bf16 [B,H,T,D] (Q pre-scaled by 1/8)
    const int gsm = 2 * GSTG;  // 192 KB
    cudaFuncSetAttribute(gemm_bf16x3<0>, cudaFuncAttributeMaxDynamicSharedMemorySize, gsm);
    cudaFuncSetAttribute(gemm_bf16x3<1>, cudaFuncAttributeMaxDynamicSharedMemorySize, gsm);
    dim3 ggrid(CC/256, MM/128);   // (4, 32) = 128 CTAs, single wave
    gemm_bf16x3<0><<<ggrid, 256, gsm>>>(xh, xl, wh + 0*CC*CC, wl + 0*CC*CC, bq,
                                        nullptr, qh, ql, 0.125f);
    gemm_bf16x3<0><<<ggrid, 256, gsm>>>(xh, xl, wh + 1*CC*CC, wl + 1*CC*CC, bk,
                                        nullptr, kh, kl, 1.0f);
    gemm_bf16x3<0><<<ggrid, 256, gsm>>>(xh, xl, wh + 2*CC*CC, wl + 2*CC*CC, bv,
                                        nullptr, vh, vl, 1.0f);

    // 4. tensor-core flash attention
    const int asm_sz = 98304;
    cudaFuncSetAttribute(attn_mma, cudaFuncAttributeMaxDynamicSharedMemorySize, asm_sz);
    attn_mma<<<dim3(TT/128, BB*HH), 256, asm_sz>>>();

    // 5. output projection -> d_out (fp32)
    gemm_bf16x3<1><<<ggrid, 256, gsm>>>(ah, al, wh + 3*CC*CC, wl + 3*CC*CC, bo,
                                        out, nullptr, nullptr, 1.0f);
}